// round 3
// baseline (speedup 1.0000x reference)
#include <cuda_runtime.h>

// VQ: x [N=131072, D=64] fp32, embeddings [D=64, K=512] fp32.
// out[0..N*D) = quantized rows (straight-through), out[out_size-1] = loss.
//
// Numerics: replicate the reference's rounding exactly:
//   dist_k = fl32( fl32(F + E_k) - 2*S_k ),  F = seq-sum fl(f_d^2),
//   E_k = seq-sum fl(e_dk^2), S_k = fma-accumulated dot.
// Strict-< argmin => first (lowest-index) minimum, matching jnp.argmin ties.

#define D       64
#define K       512
#define THREADS 256
#define VECS    256
#define ESTRIDE 68     // padded row stride (floats) for transposed emb: 272B, 16B-aligned
#define XPAD    68

typedef unsigned long long u64;

__device__ float g_err_sum;

__global__ void vq_zero_acc() { g_err_sum = 0.0f; }

__global__ void vq_finalize(float* __restrict__ out, int n_x, int loss_idx) {
    out[loss_idx] = 1.25f * g_err_sum / (float)n_x;
}

#define PACK2(dst, lo, hi) \
    asm("mov.b64 %0, {%1, %2};" : "=l"(dst) : "f"(lo), "f"(hi))
#define UNPACK2(lo, hi, src) \
    asm("mov.b64 {%0, %1}, %2;" : "=f"(lo), "=f"(hi) : "l"(src))
#define FMA2(acc, a, b) \
    asm("fma.rn.f32x2 %0, %1, %2, %0;" : "+l"(acc) : "l"(a), "l"(b))
#define ADD2(dst, a, b) \
    asm("add.rn.f32x2 %0, %1, %2;" : "=l"(dst) : "l"(a), "l"(b))

__global__ __launch_bounds__(THREADS, 1)
void vq_main(const float* __restrict__ x, const float* __restrict__ emb,
             float* __restrict__ out) {
    extern __shared__ float smem[];
    float* eT  = smem;                    // [K][ESTRIDE] transposed embeddings
    float* en2 = eT + K * ESTRIDE;        // [K]
    float* xS  = en2 + K;                 // [VECS][XPAD]

    const int tid = threadIdx.x;
    const long vbase = (long)blockIdx.x * VECS;

    // ---- stage embeddings, transposed: eT[k][d] = emb[d*K + k] ----
    #pragma unroll 4
    for (int i = tid; i < D * K; i += THREADS) {
        int d = i >> 9;          // i / K
        int k = i & (K - 1);     // i % K
        eT[k * ESTRIDE + d] = emb[i];
    }

    // ---- stage x tile (coalesced gmem read) ----
    const float* xg = x + vbase * D;
    #pragma unroll 4
    for (int i = tid; i < VECS * D; i += THREADS)
        xS[(i >> 6) * XPAD + (i & 63)] = xg[i];

    __syncthreads();

    // ---- E_k = sequential sum of fl(e^2), matching jnp.sum(e*e, axis=0) ----
    for (int k = tid; k < K; k += THREADS) {
        const float* er = eT + k * ESTRIDE;
        float s = 0.0f;
        #pragma unroll
        for (int d = 0; d < D; d++) {
            float v = er[d];
            s = __fadd_rn(s, __fmul_rn(v, v));
        }
        en2[k] = s;
    }
    __syncthreads();

    // ---- load own vector: pack (f[2j], f[2j+1]) pairs; F = seq sum fl(f^2) ----
    u64 fx2[D / 2];
    float F = 0.0f;
    {
        const float4* xrow = (const float4*)(xS + tid * XPAD);
        #pragma unroll
        for (int i = 0; i < D / 4; i++) {
            float4 v = xrow[i];
            PACK2(fx2[2 * i + 0], v.x, v.y);
            PACK2(fx2[2 * i + 1], v.z, v.w);
            F = __fadd_rn(F, __fmul_rn(v.x, v.x));
            F = __fadd_rn(F, __fmul_rn(v.y, v.y));
            F = __fadd_rn(F, __fmul_rn(v.z, v.z));
            F = __fadd_rn(F, __fmul_rn(v.w, v.w));
        }
    }

    // ---- argmin over K codes: d-lane packed f32x2 dot per code ----
    float best = 3.4e38f;
    int bestk = 0;

    #pragma unroll 2
    for (int k = 0; k < K; k++) {
        const float4* er = (const float4*)(eT + k * ESTRIDE);  // broadcast reads
        u64 a0 = 0ULL, a1 = 0ULL;
        #pragma unroll
        for (int i = 0; i < D / 4; i++) {
            float4 ev = er[i];                 // LDS.128, all lanes same addr
            u64 b0, b1;
            PACK2(b0, ev.x, ev.y);
            PACK2(b1, ev.z, ev.w);
            FMA2(a0, fx2[2 * i + 0], b0);
            FMA2(a1, fx2[2 * i + 1], b1);
        }
        u64 asum; ADD2(asum, a0, a1);
        float lo, hi; UNPACK2(lo, hi, asum);
        float s = __fadd_rn(lo, hi);           // dot_k
        float FE = __fadd_rn(F, en2[k]);       // fl(F + E_k)  -- reference rounding
        float dist = fmaf(-2.0f, s, FE);       // fl(FE - 2s)  -- same as ref subtract
        if (dist < best) { best = dist; bestk = k; }
    }

    // ---- error accumulation + write quantized row into own x-tile row ----
    float err = 0.0f;
    {
        const float* qr = eT + bestk * ESTRIDE;
        float* frow = xS + tid * XPAD;
        #pragma unroll
        for (int d = 0; d < D; d++) {
            float q = qr[d];
            float diff = frow[d] - q;
            err = fmaf(diff, diff, err);
            frow[d] = q;                       // own row only
        }
    }
    __syncthreads();

    // ---- coalesced store ----
    float* og = out + vbase * D;
    #pragma unroll 4
    for (int i = tid; i < VECS * D; i += THREADS)
        og[i] = xS[(i >> 6) * XPAD + (i & 63)];

    // ---- block reduce err, atomic into global ----
    __shared__ float red[THREADS];
    red[tid] = err;
    __syncthreads();
    #pragma unroll
    for (int s = THREADS / 2; s > 0; s >>= 1) {
        if (tid < s) red[tid] += red[tid + s];
        __syncthreads();
    }
    if (tid == 0) atomicAdd(&g_err_sum, red[0]);
}

extern "C" void kernel_launch(void* const* d_in, const int* in_sizes, int n_in,
                              void* d_out, int out_size) {
    const float* x   = (const float*)d_in[0];
    const float* emb = (const float*)d_in[1];
    float* out = (float*)d_out;

    const int n_x   = in_sizes[0];
    const int n_vec = n_x / D;       // 131072
    const int grid  = n_vec / VECS;  // 512

    const size_t smem_bytes =
        (size_t)(K * ESTRIDE + K + VECS * XPAD) * sizeof(float); // 210944 B
    cudaFuncSetAttribute(vq_main, cudaFuncAttributeMaxDynamicSharedMemorySize,
                         (int)smem_bytes);

    vq_zero_acc<<<1, 1>>>();
    vq_main<<<grid, THREADS, smem_bytes>>>(x, emb, out);
    vq_finalize<<<1, 1>>>(out, n_x, out_size - 1);
}

// round 4
// speedup vs baseline: 1.0196x; 1.0196x over previous
#include <cuda_runtime.h>

// VQ: x [N=131072, D=64] fp32, embeddings [D=64, K=512] fp32.
// out[0..N*D) = quantized rows (straight-through), out[out_size-1] = loss.
//
// Numerics (frozen — matches reference rounding, passed R3 at 8.5e-7):
//   dist_k = fl32( fl32(F + E_k) - 2*S_k ),  F = seq-sum fl(f_d^2),
//   E_k = seq-sum fl(e_dk^2), S_k = fma f32x2 dot (even/odd chains, lo+hi).
// Strict-< argmin => lowest-index tie-break (jnp.argmin).

#define D       64
#define K       512
#define THREADS 256
#define VECS    256
#define ESTRIDE 68     // floats; 272 B row stride, 16B-aligned for LDS.128
#define XPAD    68

typedef unsigned long long u64;

__device__ float g_err_sum;

__global__ void vq_zero_acc() { g_err_sum = 0.0f; }

__global__ void vq_finalize(float* __restrict__ out, int n_x, int loss_idx) {
    out[loss_idx] = 1.25f * g_err_sum / (float)n_x;
}

#define UNPACK2(lo, hi, src) \
    asm("mov.b64 {%0, %1}, %2;" : "=f"(lo), "=f"(hi) : "l"(src))
#define FMA2(acc, a, b) \
    asm("fma.rn.f32x2 %0, %1, %2, %0;" : "+l"(acc) : "l"(a), "l"(b))
#define ADD2(dst, a, b) \
    asm("add.rn.f32x2 %0, %1, %2;" : "=l"(dst) : "l"(a), "l"(b))

__global__ __launch_bounds__(THREADS, 1)
void vq_main(const float* __restrict__ x, const float* __restrict__ emb,
             float* __restrict__ out) {
    extern __shared__ float smem[];
    float* eT  = smem;                    // [K][ESTRIDE] transposed embeddings
    float* en2 = eT + K * ESTRIDE;        // [K]
    float* xS  = en2 + K;                 // [VECS][XPAD]

    const int tid = threadIdx.x;
    const long vbase = (long)blockIdx.x * VECS;

    // ---- stage embeddings transposed: eT[k][d] = emb[d*K + k] ----
    #pragma unroll 4
    for (int i = tid; i < D * K; i += THREADS) {
        int d = i >> 9;
        int k = i & (K - 1);
        eT[k * ESTRIDE + d] = emb[i];
    }

    // ---- stage x tile (coalesced) ----
    const float* xg = x + vbase * D;
    #pragma unroll 4
    for (int i = tid; i < VECS * D; i += THREADS)
        xS[(i >> 6) * XPAD + (i & 63)] = xg[i];

    __syncthreads();

    // ---- E_k = sequential sum of fl(e^2) (reference rounding) ----
    for (int k = tid; k < K; k += THREADS) {
        const float* er = eT + k * ESTRIDE;
        float s = 0.0f;
        #pragma unroll
        for (int d = 0; d < D; d++) {
            float v = er[d];
            s = __fadd_rn(s, __fmul_rn(v, v));
        }
        en2[k] = s;
    }
    __syncthreads();

    // ---- own vector: consecutive-d pairs load directly as u64 (no packs) ----
    u64 fx2[D / 2];
    float F = 0.0f;
    {
        const ulonglong2* xr = (const ulonglong2*)(xS + tid * XPAD);
        #pragma unroll
        for (int i = 0; i < D / 4; i++) {
            ulonglong2 v = xr[i];          // LDS.128 -> two f32x2 operands
            fx2[2 * i + 0] = v.x;
            fx2[2 * i + 1] = v.y;
            float x0, x1, x2, x3;
            UNPACK2(x0, x1, v.x);
            UNPACK2(x2, x3, v.y);
            F = __fadd_rn(F, __fmul_rn(x0, x0));
            F = __fadd_rn(F, __fmul_rn(x1, x1));
            F = __fadd_rn(F, __fmul_rn(x2, x2));
            F = __fadd_rn(F, __fmul_rn(x3, x3));
        }
    }

    // ---- argmin over K codes: pure LDS.128 + FFMA2 inner loop ----
    float best = 3.4e38f;
    int bestk = 0;

    for (int k = 0; k < K; k++) {
        const ulonglong2* er = (const ulonglong2*)(eT + k * ESTRIDE);
        u64 a0 = 0ULL, a1 = 0ULL;
        #pragma unroll
        for (int i = 0; i < D / 4; i++) {
            ulonglong2 b = er[i];          // broadcast LDS.128, 16B-aligned
            FMA2(a0, fx2[2 * i + 0], b.x);
            FMA2(a1, fx2[2 * i + 1], b.y);
        }
        u64 asum; ADD2(asum, a0, a1);
        float lo, hi; UNPACK2(lo, hi, asum);
        float s = __fadd_rn(lo, hi);           // dot_k
        float FE = __fadd_rn(F, en2[k]);       // fl(F + E_k)
        float dist = fmaf(-2.0f, s, FE);       // fl(FE - 2*dot)
        if (dist < best) { best = dist; bestk = k; }
    }

    // ---- gather winning code, accumulate error, overwrite own x row ----
    float err = 0.0f;
    {
        const float* qr = eT + bestk * ESTRIDE;
        float* frow = xS + tid * XPAD;
        #pragma unroll
        for (int d = 0; d < D; d++) {
            float q = qr[d];
            float diff = frow[d] - q;
            err = fmaf(diff, diff, err);
            frow[d] = q;
        }
    }
    __syncthreads();

    // ---- coalesced store of quantized tile ----
    float* og = out + vbase * D;
    #pragma unroll 4
    for (int i = tid; i < VECS * D; i += THREADS)
        og[i] = xS[(i >> 6) * XPAD + (i & 63)];

    // ---- block reduce err ----
    __shared__ float red[THREADS];
    red[tid] = err;
    __syncthreads();
    #pragma unroll
    for (int s = THREADS / 2; s > 0; s >>= 1) {
        if (tid < s) red[tid] += red[tid + s];
        __syncthreads();
    }
    if (tid == 0) atomicAdd(&g_err_sum, red[0]);
}

extern "C" void kernel_launch(void* const* d_in, const int* in_sizes, int n_in,
                              void* d_out, int out_size) {
    const float* x   = (const float*)d_in[0];
    const float* emb = (const float*)d_in[1];
    float* out = (float*)d_out;

    const int n_x   = in_sizes[0];
    const int n_vec = n_x / D;       // 131072
    const int grid  = n_vec / VECS;  // 512

    const size_t smem_bytes =
        (size_t)(K * ESTRIDE + K + VECS * XPAD) * sizeof(float); // 210944 B
    cudaFuncSetAttribute(vq_main, cudaFuncAttributeMaxDynamicSharedMemorySize,
                         (int)smem_bytes);

    vq_zero_acc<<<1, 1>>>();
    vq_main<<<grid, THREADS, smem_bytes>>>(x, emb, out);
    vq_finalize<<<1, 1>>>(out, n_x, out_size - 1);
}

// round 5
// speedup vs baseline: 1.2653x; 1.2410x over previous
#include <cuda_runtime.h>

// VQ: x [N=131072, D=64] fp32, embeddings [D=64, K=512] fp32.
// out[0..N*D) = quantized rows (straight-through), out[out_size-1] = loss.
//
// Numerics (frozen — matches reference rounding, passed R3/R4 at 8.5e-7):
//   dist_k = fl32( fl32(F + E_k) - 2*S_k ),  F = seq-sum fl(f_d^2),
//   E_k = seq-sum fl(e_dk^2), S_k = f32x2 FMA dot (even/odd chains, lo+hi).
// Strict-< argmin => lowest-index tie-break (jnp.argmin).
//
// R5 structure: 2 vectors per thread (register-blocked), codebook-only smem,
// direct LDG/STG for x/out rows. Each broadcast LDS feeds 4 FFMA2.

#define D       64
#define K       512
#define THREADS 256
#define VPT     2
#define VECS    (THREADS * VPT)   // 512 vectors per block
#define ESTRIDE 68                // 272 B row stride: 16B-aligned, 8-way (not 32) conflicts

typedef unsigned long long u64;

__device__ float g_err_sum;

__global__ void vq_zero_acc() { g_err_sum = 0.0f; }

__global__ void vq_finalize(float* __restrict__ out, int n_x, int loss_idx) {
    out[loss_idx] = 1.25f * g_err_sum / (float)n_x;
}

#define UNPACK2(lo, hi, src) \
    asm("mov.b64 {%0, %1}, %2;" : "=f"(lo), "=f"(hi) : "l"(src))
#define FMA2(acc, a, b) \
    asm("fma.rn.f32x2 %0, %1, %2, %0;" : "+l"(acc) : "l"(a), "l"(b))
#define ADD2(dst, a, b) \
    asm("add.rn.f32x2 %0, %1, %2;" : "=l"(dst) : "l"(a), "l"(b))

__global__ __launch_bounds__(THREADS, 1)
void vq_main(const float* __restrict__ x, const float* __restrict__ emb,
             float* __restrict__ out) {
    extern __shared__ float smem[];
    float* eT  = smem;                    // [K][ESTRIDE] transposed embeddings
    float* en2 = eT + K * ESTRIDE;        // [K]
    float* red = en2 + K;                 // [THREADS]

    const int tid = threadIdx.x;
    const long vbase = (long)blockIdx.x * VECS;

    // ---- stage embeddings transposed: eT[k][d] = emb[d*K + k] ----
    #pragma unroll 4
    for (int i = tid; i < D * K; i += THREADS) {
        int d = i >> 9;
        int k = i & (K - 1);
        eT[k * ESTRIDE + d] = emb[i];
    }
    __syncthreads();

    // ---- E_k = sequential sum of fl(e^2) (reference rounding) ----
    for (int k = tid; k < K; k += THREADS) {
        const float* er = eT + k * ESTRIDE;
        float s = 0.0f;
        #pragma unroll
        for (int d = 0; d < D; d++) {
            float v = er[d];
            s = __fadd_rn(s, __fmul_rn(v, v));
        }
        en2[k] = s;
    }
    __syncthreads();

    // ---- load this thread's 2 vectors straight from gmem (16B-aligned rows) ----
    const ulonglong2* xr0 = (const ulonglong2*)(x + (vbase + tid) * D);
    const ulonglong2* xr1 = (const ulonglong2*)(x + (vbase + THREADS + tid) * D);

    u64 fA[D / 2], fB[D / 2];
    float F0 = 0.0f, F1 = 0.0f;
    #pragma unroll
    for (int i = 0; i < D / 4; i++) {
        ulonglong2 va = xr0[i];
        fA[2 * i + 0] = va.x;  fA[2 * i + 1] = va.y;
        float a0, a1, a2, a3;
        UNPACK2(a0, a1, va.x); UNPACK2(a2, a3, va.y);
        F0 = __fadd_rn(F0, __fmul_rn(a0, a0));
        F0 = __fadd_rn(F0, __fmul_rn(a1, a1));
        F0 = __fadd_rn(F0, __fmul_rn(a2, a2));
        F0 = __fadd_rn(F0, __fmul_rn(a3, a3));

        ulonglong2 vb = xr1[i];
        fB[2 * i + 0] = vb.x;  fB[2 * i + 1] = vb.y;
        float b0, b1, b2, b3;
        UNPACK2(b0, b1, vb.x); UNPACK2(b2, b3, vb.y);
        F1 = __fadd_rn(F1, __fmul_rn(b0, b0));
        F1 = __fadd_rn(F1, __fmul_rn(b1, b1));
        F1 = __fadd_rn(F1, __fmul_rn(b2, b2));
        F1 = __fadd_rn(F1, __fmul_rn(b3, b3));
    }

    // ---- argmin over K codes: each broadcast LDS.128 feeds 4 FFMA2 ----
    float best0 = 3.4e38f, best1 = 3.4e38f;
    int bk0 = 0, bk1 = 0;

    for (int k = 0; k < K; k++) {
        const ulonglong2* er = (const ulonglong2*)(eT + k * ESTRIDE);
        u64 a0 = 0ULL, a1 = 0ULL, c0 = 0ULL, c1 = 0ULL;
        #pragma unroll
        for (int i = 0; i < D / 4; i++) {
            ulonglong2 e = er[i];          // broadcast LDS.128
            FMA2(a0, fA[2 * i + 0], e.x);
            FMA2(a1, fA[2 * i + 1], e.y);
            FMA2(c0, fB[2 * i + 0], e.x);
            FMA2(c1, fB[2 * i + 1], e.y);
        }
        float e2 = en2[k];

        u64 s01; ADD2(s01, a0, a1);
        float lo0, hi0; UNPACK2(lo0, hi0, s01);
        float s0 = __fadd_rn(lo0, hi0);
        float d0 = fmaf(-2.0f, s0, __fadd_rn(F0, e2));
        if (d0 < best0) { best0 = d0; bk0 = k; }

        u64 s23; ADD2(s23, c0, c1);
        float lo1, hi1; UNPACK2(lo1, hi1, s23);
        float s1 = __fadd_rn(lo1, hi1);
        float d1 = fmaf(-2.0f, s1, __fadd_rn(F1, e2));
        if (d1 < best1) { best1 = d1; bk1 = k; }
    }

    // ---- error + direct quantized-row store (bit-exact code rows) ----
    float err = 0.0f;
    {
        const ulonglong2* qr = (const ulonglong2*)(eT + bk0 * ESTRIDE);
        ulonglong2* og = (ulonglong2*)(out + (vbase + tid) * D);
        #pragma unroll
        for (int i = 0; i < D / 4; i++) {
            ulonglong2 q = qr[i];
            float q0, q1, q2, q3, f0, f1, f2, f3;
            UNPACK2(q0, q1, q.x); UNPACK2(q2, q3, q.y);
            UNPACK2(f0, f1, fA[2 * i + 0]); UNPACK2(f2, f3, fA[2 * i + 1]);
            float u0 = f0 - q0, u1 = f1 - q1, u2 = f2 - q2, u3 = f3 - q3;
            err = fmaf(u0, u0, err); err = fmaf(u1, u1, err);
            err = fmaf(u2, u2, err); err = fmaf(u3, u3, err);
            og[i] = q;
        }
    }
    {
        const ulonglong2* qr = (const ulonglong2*)(eT + bk1 * ESTRIDE);
        ulonglong2* og = (ulonglong2*)(out + (vbase + THREADS + tid) * D);
        #pragma unroll
        for (int i = 0; i < D / 4; i++) {
            ulonglong2 q = qr[i];
            float q0, q1, q2, q3, f0, f1, f2, f3;
            UNPACK2(q0, q1, q.x); UNPACK2(q2, q3, q.y);
            UNPACK2(f0, f1, fB[2 * i + 0]); UNPACK2(f2, f3, fB[2 * i + 1]);
            float u0 = f0 - q0, u1 = f1 - q1, u2 = f2 - q2, u3 = f3 - q3;
            err = fmaf(u0, u0, err); err = fmaf(u1, u1, err);
            err = fmaf(u2, u2, err); err = fmaf(u3, u3, err);
            og[i] = q;
        }
    }

    // ---- block reduce err ----
    red[tid] = err;
    __syncthreads();
    #pragma unroll
    for (int s = THREADS / 2; s > 0; s >>= 1) {
        if (tid < s) red[tid] += red[tid + s];
        __syncthreads();
    }
    if (tid == 0) atomicAdd(&g_err_sum, red[0]);
}

extern "C" void kernel_launch(void* const* d_in, const int* in_sizes, int n_in,
                              void* d_out, int out_size) {
    const float* x   = (const float*)d_in[0];
    const float* emb = (const float*)d_in[1];
    float* out = (float*)d_out;

    const int n_x   = in_sizes[0];
    const int n_vec = n_x / D;       // 131072
    const int grid  = n_vec / VECS;  // 256

    const size_t smem_bytes =
        (size_t)(K * ESTRIDE + K + THREADS) * sizeof(float); // 142336 B
    cudaFuncSetAttribute(vq_main, cudaFuncAttributeMaxDynamicSharedMemorySize,
                         (int)smem_bytes);

    vq_zero_acc<<<1, 1>>>();
    vq_main<<<grid, THREADS, smem_bytes>>>(x, emb, out);
    vq_finalize<<<1, 1>>>(out, n_x, out_size - 1);
}

// round 7
// speedup vs baseline: 1.4807x; 1.1702x over previous
#include <cuda_runtime.h>
#include <cstdint>

// VQ via legacy mma.sync tf32 split-precision GEMM (sm_103-safe, no tcgen05).
// x [131072, 64] fp32, emb [64, 512] fp32.
// out[0..N*D) = quantized rows, out[out_size-1] = 1.25 * mean((q-x)^2).
//
// Numerics frozen (R3/R4/R5-validated):
//   dist_k = fl32( fl32(F + E_k) - 2*S_k ), F/E_k exact fp32 seq sums,
//   S via tf32-split MMA (hi*hi + hi*lo + lo*hi), lowest-index tie-break.

#define D        64
#define K        512
#define TILE_M   128
#define THREADS  256
#define PAD      68      // padded row stride in floats (conflict-free frag loads)

typedef unsigned long long u64;
typedef unsigned int       u32;

// ---------------- device scratch ----------------
__device__ float g_embT[K * D];   // [512][64] codebook rows (fp32)
__device__ u32   g_Bhi[K * D];    // tf32 hi image, row-major [k][d]
__device__ u32   g_Blo[K * D];    // tf32 lo image
__device__ float g_en2[K];
__device__ float g_err_sum;
__device__ u32   g_done;

__device__ __forceinline__ u32 tf32_rna(float v) {
    u32 r; asm("cvt.rna.tf32.f32 %0, %1;" : "=r"(r) : "f"(v)); return r;
}

#define MMA_TF32(c0, c1, c2, c3, a0, a1, a2, a3, b0, b1)                     \
    asm volatile("mma.sync.aligned.m16n8k8.row.col.f32.tf32.tf32.f32 "      \
                 "{%0,%1,%2,%3}, {%4,%5,%6,%7}, {%8,%9}, {%0,%1,%2,%3};"    \
                 : "+f"(c0), "+f"(c1), "+f"(c2), "+f"(c3)                   \
                 : "r"(a0), "r"(a1), "r"(a2), "r"(a3), "r"(b0), "r"(b1))

// ---------------- precompute ----------------
__global__ void vq_pre(const float* __restrict__ emb) {
    int gt = blockIdx.x * blockDim.x + threadIdx.x;
    int stride = gridDim.x * blockDim.x;
    if (gt == 0) { g_err_sum = 0.0f; g_done = 0u; }
    for (int i = gt; i < K * D; i += stride) {
        int k = i >> 6, d = i & 63;
        float v = emb[d * K + k];
        g_embT[i] = v;
        u32 hib = tf32_rna(v);
        float lo = __fsub_rn(v, __uint_as_float(hib));
        g_Bhi[i] = hib;
        g_Blo[i] = tf32_rna(lo);
    }
    for (int k = gt; k < K; k += stride) {
        float s = 0.0f;
        for (int d = 0; d < D; d++) {
            float v = emb[d * K + k];
            s = __fadd_rn(s, __fmul_rn(v, v));
        }
        g_en2[k] = s;
    }
}

// ---------------- smem layout (float indices) ----------------
#define SM_AHI   0
#define SM_ALO   (SM_AHI + TILE_M * PAD)        // 8704
#define SM_BHI   (SM_ALO + TILE_M * PAD)        // 17408
#define SM_BLO   (SM_BHI + 256 * PAD)           // 34816
#define SM_EN2   (SM_BLO + 256 * PAD)           // 52224
#define SM_F     (SM_EN2 + K)                   // 52736
#define SM_RED   (SM_F + TILE_M)                // 52864
#define SM_PM    (SM_RED + THREADS)             // 53120  (u64 x 128 = 256 floats)
#define SMEM_FLOATS (SM_PM + 2 * TILE_M)        // 53376
#define SMEM_SZ  (SMEM_FLOATS * 4)              // 213504 B

__global__ __launch_bounds__(THREADS, 1)
void vq_main(const float* __restrict__ x, float* __restrict__ out,
             int n_x, int loss_idx, int nblocks) {
    extern __shared__ float smem[];
    float* Ahi = smem + SM_AHI;
    float* Alo = smem + SM_ALO;
    float* Bhi = smem + SM_BHI;
    float* Blo = smem + SM_BLO;
    float* en2s = smem + SM_EN2;
    float* Fs   = smem + SM_F;
    float* red  = smem + SM_RED;
    u64*   pm   = (u64*)(smem + SM_PM);

    const int tid = threadIdx.x;
    const int wid = tid >> 5, lid = tid & 31;
    const int g = lid >> 2, t = lid & 3;       // mma group / thread-in-group
    const long mbase = (long)blockIdx.x * TILE_M;

    // ---- en2 -> smem ----
    for (int i = tid; i < K; i += THREADS) en2s[i] = g_en2[i];

    // ---- stage A tile: tf32 hi/lo, padded rows ----
    {
        const float4* xg = (const float4*)(x + mbase * D);
        #pragma unroll
        for (int i = tid; i < TILE_M * D / 4; i += THREADS) {
            int row = i >> 4, col4 = (i & 15) * 4;
            float4 v = xg[i];
            u32 h0 = tf32_rna(v.x), h1 = tf32_rna(v.y), h2 = tf32_rna(v.z), h3 = tf32_rna(v.w);
            u32 l0 = tf32_rna(__fsub_rn(v.x, __uint_as_float(h0)));
            u32 l1 = tf32_rna(__fsub_rn(v.y, __uint_as_float(h1)));
            u32 l2 = tf32_rna(__fsub_rn(v.z, __uint_as_float(h2)));
            u32 l3 = tf32_rna(__fsub_rn(v.w, __uint_as_float(h3)));
            int o = row * PAD + col4;
            *(uint4*)(Ahi + o) = make_uint4(h0, h1, h2, h3);
            *(uint4*)(Alo + o) = make_uint4(l0, l1, l2, l3);
        }
    }

    // ---- F per row (reference sequential order), threads 0-127 ----
    if (tid < TILE_M) {
        const float4* xr = (const float4*)(x + (mbase + tid) * D);
        float F = 0.0f;
        #pragma unroll
        for (int i = 0; i < D / 4; i++) {
            float4 v = xr[i];
            F = __fadd_rn(F, __fmul_rn(v.x, v.x));
            F = __fadd_rn(F, __fmul_rn(v.y, v.y));
            F = __fadd_rn(F, __fmul_rn(v.z, v.z));
            F = __fadd_rn(F, __fmul_rn(v.w, v.w));
        }
        Fs[tid] = F;
    }
    __syncthreads();

    // ---- load A fragments (all 8 k-steps, hi & lo) ----
    const int rbase = wid * 16;
    u32 ah[8][4], al[8][4];
    {
        const int r0 = (rbase + g) * PAD, r1 = (rbase + g + 8) * PAD;
        #pragma unroll
        for (int ks = 0; ks < 8; ks++) {
            int c = ks * 8 + t;
            ah[ks][0] = __float_as_uint(Ahi[r0 + c]);
            ah[ks][1] = __float_as_uint(Ahi[r1 + c]);
            ah[ks][2] = __float_as_uint(Ahi[r0 + c + 4]);
            ah[ks][3] = __float_as_uint(Ahi[r1 + c + 4]);
            al[ks][0] = __float_as_uint(Alo[r0 + c]);
            al[ks][1] = __float_as_uint(Alo[r1 + c]);
            al[ks][2] = __float_as_uint(Alo[r0 + c + 4]);
            al[ks][3] = __float_as_uint(Alo[r1 + c + 4]);
        }
    }

    const float Fg  = Fs[rbase + g];
    const float Fg8 = Fs[rbase + g + 8];
    u64 pb0 = ~0ULL, pb1 = ~0ULL;

    // ---- two code halves of 256 ----
    for (int h = 0; h < 2; h++) {
        // stage B half: copy precomputed tf32 images into padded rows
        {
            const uint4* shi = (const uint4*)(g_Bhi + h * 256 * D);
            const uint4* slo = (const uint4*)(g_Blo + h * 256 * D);
            #pragma unroll
            for (int i = tid; i < 256 * D / 4; i += THREADS) {
                int row = i >> 4, col4 = (i & 15) * 4;
                int o = row * PAD + col4;
                *(uint4*)(Bhi + o) = shi[i];
                *(uint4*)(Blo + o) = slo[i];
            }
        }
        __syncthreads();

        #pragma unroll 2
        for (int c = 0; c < 32; c++) {
            const int brow = (c * 8 + g) * PAD;
            u32 bh[16], bl[16];
            #pragma unroll
            for (int ks = 0; ks < 8; ks++) {
                int o = brow + ks * 8 + t;
                bh[2 * ks]     = __float_as_uint(Bhi[o]);
                bh[2 * ks + 1] = __float_as_uint(Bhi[o + 4]);
                bl[2 * ks]     = __float_as_uint(Blo[o]);
                bl[2 * ks + 1] = __float_as_uint(Blo[o + 4]);
            }
            // three independent accumulation chains
            float A0 = 0, A1 = 0, A2 = 0, A3 = 0;
            float B0 = 0, B1 = 0, B2 = 0, B3 = 0;
            float C0 = 0, C1 = 0, C2 = 0, C3 = 0;
            #pragma unroll
            for (int ks = 0; ks < 8; ks++) {
                MMA_TF32(A0, A1, A2, A3, ah[ks][0], ah[ks][1], ah[ks][2], ah[ks][3],
                         bh[2 * ks], bh[2 * ks + 1]);
                MMA_TF32(B0, B1, B2, B3, ah[ks][0], ah[ks][1], ah[ks][2], ah[ks][3],
                         bl[2 * ks], bl[2 * ks + 1]);
                MMA_TF32(C0, C1, C2, C3, al[ks][0], al[ks][1], al[ks][2], al[ks][3],
                         bh[2 * ks], bh[2 * ks + 1]);
            }
            const int cbase = h * 256 + c * 8 + 2 * t;
            float2 e2 = *(float2*)(en2s + cbase);
            float FEg0  = __fadd_rn(Fg, e2.x),  FEg1  = __fadd_rn(Fg, e2.y);
            float FEg80 = __fadd_rn(Fg8, e2.x), FEg81 = __fadd_rn(Fg8, e2.y);
            float s00 = __fadd_rn(__fadd_rn(A0, B0), C0);
            float s01 = __fadd_rn(__fadd_rn(A1, B1), C1);
            float s10 = __fadd_rn(__fadd_rn(A2, B2), C2);
            float s11 = __fadd_rn(__fadd_rn(A3, B3), C3);
            float d00 = fmaf(-2.0f, s00, FEg0);
            float d01 = fmaf(-2.0f, s01, FEg1);
            float d10 = fmaf(-2.0f, s10, FEg80);
            float d11 = fmaf(-2.0f, s11, FEg81);
            u64 p;
            p = ((u64)__float_as_uint(d00) << 9) | (u32)(cbase);     if (p < pb0) pb0 = p;
            p = ((u64)__float_as_uint(d01) << 9) | (u32)(cbase + 1); if (p < pb0) pb0 = p;
            p = ((u64)__float_as_uint(d10) << 9) | (u32)(cbase);     if (p < pb1) pb1 = p;
            p = ((u64)__float_as_uint(d11) << 9) | (u32)(cbase + 1); if (p < pb1) pb1 = p;
        }
        __syncthreads();   // before overwriting B smem with next half
    }

    // ---- reduce best across the 4 threads of each mma group ----
    #pragma unroll
    for (int off = 1; off < 4; off <<= 1) {
        u64 q0 = __shfl_xor_sync(0xffffffffu, pb0, off);
        u64 q1 = __shfl_xor_sync(0xffffffffu, pb1, off);
        if (q0 < pb0) pb0 = q0;
        if (q1 < pb1) pb1 = q1;
    }
    if (t == 0) {
        pm[rbase + g]     = pb0;
        pm[rbase + g + 8] = pb1;
    }
    __syncthreads();

    // ---- gather winning code row, error, store ----
    float err = 0.0f;
    if (tid < TILE_M) {
        int kst = (int)(pm[tid] & 511ULL);
        const float4* qr = (const float4*)(g_embT + kst * D);
        const float4* xr = (const float4*)(x + (mbase + tid) * D);
        float4* og = (float4*)(out + (mbase + tid) * D);
        #pragma unroll
        for (int i = 0; i < D / 4; i++) {
            float4 q = qr[i], v = xr[i];
            float u0 = v.x - q.x, u1 = v.y - q.y, u2 = v.z - q.z, u3 = v.w - q.w;
            err = fmaf(u0, u0, err); err = fmaf(u1, u1, err);
            err = fmaf(u2, u2, err); err = fmaf(u3, u3, err);
            og[i] = q;
        }
    }

    // ---- loss reduce + last-block finalize ----
    red[tid] = err;
    __syncthreads();
    #pragma unroll
    for (int s = THREADS / 2; s > 0; s >>= 1) {
        if (tid < s) red[tid] += red[tid + s];
        __syncthreads();
    }
    if (tid == 0) {
        atomicAdd(&g_err_sum, red[0]);
        __threadfence();
        u32 done = atomicAdd(&g_done, 1u);
        if (done == (u32)(nblocks - 1)) {
            __threadfence();
            out[loss_idx] = 1.25f * g_err_sum / (float)n_x;
        }
    }
}

extern "C" void kernel_launch(void* const* d_in, const int* in_sizes, int n_in,
                              void* d_out, int out_size) {
    const float* x   = (const float*)d_in[0];
    const float* emb = (const float*)d_in[1];
    float* out = (float*)d_out;

    const int n_x  = in_sizes[0];            // 8388608
    const int grid = n_x / D / TILE_M;       // 1024

    cudaFuncSetAttribute(vq_main, cudaFuncAttributeMaxDynamicSharedMemorySize, SMEM_SZ);

    vq_pre<<<64, 256>>>(emb);
    vq_main<<<grid, THREADS, SMEM_SZ>>>(x, out, n_x, out_size - 1, grid);
}

// round 8
// speedup vs baseline: 1.8589x; 1.2555x over previous
#include <cuda_runtime.h>
#include <cstdint>

// VQ via legacy mma.sync tf32 split-precision GEMM (sm_103-safe).
// x [131072, 64] fp32, emb [64, 512] fp32.
// out[0..N*D) = quantized rows, out[out_size-1] = 1.25 * mean((q-x)^2).
//
// R8: fragment-ordered B (LDS.128 hot loop), smem work-region reuse
// (A staging then B quarters), __launch_bounds__(256,2) for 16 warps/SM.

#define D        64
#define K        512
#define TILE_M   128
#define THREADS  256
#define PAD      68

typedef unsigned long long u64;
typedef unsigned int       u32;

// ---------------- device scratch ----------------
__device__ float g_embT[K * D];        // [512][64] codebook rows fp32
__device__ uint4 g_Bfrag[64 * 8 * 32]; // fragment-ordered tf32 B: [c][chunk][lane]
__device__ float g_en2[K];
__device__ float g_err_sum;
__device__ u32   g_done;

__device__ __forceinline__ u32 tf32_rna(float v) {
    u32 r; asm("cvt.rna.tf32.f32 %0, %1;" : "=r"(r) : "f"(v)); return r;
}

#define MMA_TF32(c0, c1, c2, c3, a0, a1, a2, a3, b0, b1)                     \
    asm volatile("mma.sync.aligned.m16n8k8.row.col.f32.tf32.tf32.f32 "      \
                 "{%0,%1,%2,%3}, {%4,%5,%6,%7}, {%8,%9}, {%0,%1,%2,%3};"    \
                 : "+f"(c0), "+f"(c1), "+f"(c2), "+f"(c3)                   \
                 : "r"(a0), "r"(a1), "r"(a2), "r"(a3), "r"(b0), "r"(b1))

// ---------------- precompute ----------------
__global__ void vq_pre(const float* __restrict__ emb) {
    int gt = blockIdx.x * blockDim.x + threadIdx.x;
    int stride = gridDim.x * blockDim.x;
    if (gt == 0) { g_err_sum = 0.0f; g_done = 0u; }

    // embT + en2
    for (int i = gt; i < K * D; i += stride) {
        int k = i >> 6, d = i & 63;
        g_embT[i] = emb[d * K + k];
    }
    for (int k = gt; k < K; k += stride) {
        float s = 0.0f;
        for (int d = 0; d < D; d++) {
            float v = emb[d * K + k];
            s = __fadd_rn(s, __fmul_rn(v, v));
        }
        g_en2[k] = s;
    }

    // fragment-ordered B: entry = [c][j][lane], j<4 = hi chunks, j>=4 = lo.
    // lane l = g*4+t, code n = c*8+g; chunk jj covers k = {16jj+t, +4, +8, +12}.
    for (int idx = gt; idx < 64 * 8 * 32; idx += stride) {
        int c = idx >> 8;
        int j = (idx >> 5) & 7;
        int l = idx & 31;
        int g = l >> 2, t = l & 3;
        int n = c * 8 + g;
        int jj = j & 3;
        bool lo = (j >= 4);
        u32 w[4];
        #pragma unroll
        for (int p = 0; p < 4; p++) {
            int k = 16 * jj + t + 4 * p;
            float v = emb[k * K + n];
            u32 hib = tf32_rna(v);
            if (!lo) w[p] = hib;
            else     w[p] = tf32_rna(__fsub_rn(v, __uint_as_float(hib)));
        }
        g_Bfrag[idx] = make_uint4(w[0], w[1], w[2], w[3]);
    }
}

// ---------------- smem layout (float indices) ----------------
#define SM_WORK  0                        // max(A 2*128*68 = 17408, B 16384)
#define SM_EN2   17408
#define SM_F     (SM_EN2 + K)             // 17920
#define SM_RED   (SM_F + TILE_M)          // 18048
#define SM_PM    (SM_RED + THREADS)       // 18304 (128 u64)
#define SMEM_FLOATS (SM_PM + 2 * TILE_M)  // 18560
#define SMEM_SZ  (SMEM_FLOATS * 4)        // 74240 B

__global__ __launch_bounds__(THREADS, 2)
void vq_main(const float* __restrict__ x, float* __restrict__ out,
             int n_x, int loss_idx, int nblocks) {
    extern __shared__ float smem[];
    float* work = smem + SM_WORK;
    float* en2s = smem + SM_EN2;
    float* Fs   = smem + SM_F;
    float* red  = smem + SM_RED;
    u64*   pm   = (u64*)(smem + SM_PM);

    const int tid = threadIdx.x;
    const int wid = tid >> 5, lid = tid & 31;
    const int g = lid >> 2, t = lid & 3;
    const long mbase = (long)blockIdx.x * TILE_M;

    for (int i = tid; i < K; i += THREADS) en2s[i] = g_en2[i];

    // ---- stage A tile into work (padded hi/lo) ----
    float* Ahi = work;
    float* Alo = work + TILE_M * PAD;
    {
        const float4* xg = (const float4*)(x + mbase * D);
        #pragma unroll
        for (int i = tid; i < TILE_M * D / 4; i += THREADS) {
            int row = i >> 4, col4 = (i & 15) * 4;
            float4 v = xg[i];
            u32 h0 = tf32_rna(v.x), h1 = tf32_rna(v.y), h2 = tf32_rna(v.z), h3 = tf32_rna(v.w);
            u32 l0 = tf32_rna(__fsub_rn(v.x, __uint_as_float(h0)));
            u32 l1 = tf32_rna(__fsub_rn(v.y, __uint_as_float(h1)));
            u32 l2 = tf32_rna(__fsub_rn(v.z, __uint_as_float(h2)));
            u32 l3 = tf32_rna(__fsub_rn(v.w, __uint_as_float(h3)));
            int o = row * PAD + col4;
            *(uint4*)(Ahi + o) = make_uint4(h0, h1, h2, h3);
            *(uint4*)(Alo + o) = make_uint4(l0, l1, l2, l3);
        }
    }
    if (tid < TILE_M) {
        const float4* xr = (const float4*)(x + (mbase + tid) * D);
        float F = 0.0f;
        #pragma unroll
        for (int i = 0; i < D / 4; i++) {
            float4 v = xr[i];
            F = __fadd_rn(F, __fmul_rn(v.x, v.x));
            F = __fadd_rn(F, __fmul_rn(v.y, v.y));
            F = __fadd_rn(F, __fmul_rn(v.z, v.z));
            F = __fadd_rn(F, __fmul_rn(v.w, v.w));
        }
        Fs[tid] = F;
    }
    __syncthreads();

    // ---- A fragments to registers ----
    const int rbase = wid * 16;
    u32 ah[8][4], al[8][4];
    {
        const int r0 = (rbase + g) * PAD, r1 = (rbase + g + 8) * PAD;
        #pragma unroll
        for (int ks = 0; ks < 8; ks++) {
            int c = ks * 8 + t;
            ah[ks][0] = __float_as_uint(Ahi[r0 + c]);
            ah[ks][1] = __float_as_uint(Ahi[r1 + c]);
            ah[ks][2] = __float_as_uint(Ahi[r0 + c + 4]);
            ah[ks][3] = __float_as_uint(Ahi[r1 + c + 4]);
            al[ks][0] = __float_as_uint(Alo[r0 + c]);
            al[ks][1] = __float_as_uint(Alo[r1 + c]);
            al[ks][2] = __float_as_uint(Alo[r0 + c + 4]);
            al[ks][3] = __float_as_uint(Alo[r1 + c + 4]);
        }
    }
    const float Fg  = Fs[rbase + g];
    const float Fg8 = Fs[rbase + g + 8];
    __syncthreads();   // all A reads done before work is reused for B

    u64 pb0 = ~0ULL, pb1 = ~0ULL;
    uint4* Bs = (uint4*)work;   // 4096 uint4 per quarter (64 KB)

    for (int q = 0; q < 4; q++) {
        // ---- stage B quarter (straight memcpy of fragments) ----
        {
            const uint4* src = g_Bfrag + q * 4096;
            #pragma unroll 4
            for (int i = tid; i < 4096; i += THREADS) Bs[i] = src[i];
        }
        __syncthreads();

        for (int cc = 0; cc < 16; cc++) {
            const uint4* bb = Bs + cc * 256 + lid;   // [chunk][lane]
            float A0 = 0, A1 = 0, A2 = 0, A3 = 0;
            float B0 = 0, B1 = 0, B2 = 0, B3 = 0;
            float C0 = 0, C1 = 0, C2 = 0, C3 = 0;
            #pragma unroll
            for (int j = 0; j < 4; j++) {
                uint4 bh = bb[j * 32];               // LDS.128, conflict-free
                uint4 bl = bb[(j + 4) * 32];
                MMA_TF32(A0, A1, A2, A3, ah[2*j][0], ah[2*j][1], ah[2*j][2], ah[2*j][3], bh.x, bh.y);
                MMA_TF32(B0, B1, B2, B3, ah[2*j][0], ah[2*j][1], ah[2*j][2], ah[2*j][3], bl.x, bl.y);
                MMA_TF32(C0, C1, C2, C3, al[2*j][0], al[2*j][1], al[2*j][2], al[2*j][3], bh.x, bh.y);
                MMA_TF32(A0, A1, A2, A3, ah[2*j+1][0], ah[2*j+1][1], ah[2*j+1][2], ah[2*j+1][3], bh.z, bh.w);
                MMA_TF32(B0, B1, B2, B3, ah[2*j+1][0], ah[2*j+1][1], ah[2*j+1][2], ah[2*j+1][3], bl.z, bl.w);
                MMA_TF32(C0, C1, C2, C3, al[2*j+1][0], al[2*j+1][1], al[2*j+1][2], al[2*j+1][3], bh.z, bh.w);
            }
            const int cbase = (q * 16 + cc) * 8 + 2 * t;
            float2 e2 = *(float2*)(en2s + cbase);
            float s00 = __fadd_rn(__fadd_rn(A0, B0), C0);
            float s01 = __fadd_rn(__fadd_rn(A1, B1), C1);
            float s10 = __fadd_rn(__fadd_rn(A2, B2), C2);
            float s11 = __fadd_rn(__fadd_rn(A3, B3), C3);
            float d00 = fmaf(-2.0f, s00, __fadd_rn(Fg,  e2.x));
            float d01 = fmaf(-2.0f, s01, __fadd_rn(Fg,  e2.y));
            float d10 = fmaf(-2.0f, s10, __fadd_rn(Fg8, e2.x));
            float d11 = fmaf(-2.0f, s11, __fadd_rn(Fg8, e2.y));
            u64 p;
            p = ((u64)__float_as_uint(d00) << 9) | (u32)(cbase);     if (p < pb0) pb0 = p;
            p = ((u64)__float_as_uint(d01) << 9) | (u32)(cbase + 1); if (p < pb0) pb0 = p;
            p = ((u64)__float_as_uint(d10) << 9) | (u32)(cbase);     if (p < pb1) pb1 = p;
            p = ((u64)__float_as_uint(d11) << 9) | (u32)(cbase + 1); if (p < pb1) pb1 = p;
        }
        __syncthreads();   // before next quarter overwrites B
    }

    // ---- reduce best across the 4 threads of each mma group ----
    #pragma unroll
    for (int off = 1; off < 4; off <<= 1) {
        u64 q0 = __shfl_xor_sync(0xffffffffu, pb0, off);
        u64 q1 = __shfl_xor_sync(0xffffffffu, pb1, off);
        if (q0 < pb0) pb0 = q0;
        if (q1 < pb1) pb1 = q1;
    }
    if (t == 0) {
        pm[rbase + g]     = pb0;
        pm[rbase + g + 8] = pb1;
    }
    __syncthreads();

    // ---- gather winning code row, error, store ----
    float err = 0.0f;
    if (tid < TILE_M) {
        int kst = (int)(pm[tid] & 511ULL);
        const float4* qr = (const float4*)(g_embT + kst * D);
        const float4* xr = (const float4*)(x + (mbase + tid) * D);
        float4* og = (float4*)(out + (mbase + tid) * D);
        #pragma unroll
        for (int i = 0; i < D / 4; i++) {
            float4 qv = qr[i], v = xr[i];
            float u0 = v.x - qv.x, u1 = v.y - qv.y, u2 = v.z - qv.z, u3 = v.w - qv.w;
            err = fmaf(u0, u0, err); err = fmaf(u1, u1, err);
            err = fmaf(u2, u2, err); err = fmaf(u3, u3, err);
            og[i] = qv;
        }
    }

    // ---- loss reduce + last-block finalize ----
    red[tid] = err;
    __syncthreads();
    #pragma unroll
    for (int s = THREADS / 2; s > 0; s >>= 1) {
        if (tid < s) red[tid] += red[tid + s];
        __syncthreads();
    }
    if (tid == 0) {
        atomicAdd(&g_err_sum, red[0]);
        __threadfence();
        u32 done = atomicAdd(&g_done, 1u);
        if (done == (u32)(nblocks - 1)) {
            __threadfence();
            out[loss_idx] = 1.25f * g_err_sum / (float)n_x;
        }
    }
}

extern "C" void kernel_launch(void* const* d_in, const int* in_sizes, int n_in,
                              void* d_out, int out_size) {
    const float* x   = (const float*)d_in[0];
    const float* emb = (const float*)d_in[1];
    float* out = (float*)d_out;

    const int n_x  = in_sizes[0];            // 8388608
    const int grid = n_x / D / TILE_M;       // 1024

    cudaFuncSetAttribute(vq_main, cudaFuncAttributeMaxDynamicSharedMemorySize, SMEM_SZ);

    vq_pre<<<64, 256>>>(emb);
    vq_main<<<grid, THREADS, SMEM_SZ>>>(x, out, n_x, out_size - 1, grid);
}